// round 14
// baseline (speedup 1.0000x reference)
#include <cuda_runtime.h>
#include <cuda.h>
#include <cuda_fp16.h>
#include <math.h>
#include <cstdint>

// ---------------------------------------------------------------------------
// Problem constants
// ---------------------------------------------------------------------------
#define NROWS 8192       // 4B rows in rep
#define HALF  4096       // rows per input
#define D     512        // embedding dim

// GEMM config: 128x256 CTA tile, 8 warps of 64x64 (fp16 acc), K chunk 64
#define TM_CTA  128
#define TN_CTA  256
#define KC      64
#define NCHUNK  (D / KC)             // 8
#define NT      256
#define NSTAGE  2
#define A_B     (TM_CTA * KC * 2)    // 16384 B per A stage
#define SLOT_B  (A_B + TN_CTA * KC * 2)  // A + B per stage = 49152 B
#define SMEM_DYN (2048 + NSTAGE * SLOT_B) // 100352 B -> 2 CTAs/SM

#define NTILES  1056                 // upper-triangular 128x256 tiles
#define GRID    296                  // persistent CTAs, 2 per SM

// rows scaled x16 -> acc = 256*dot. exp(2*dot) = ex2(acc * 2*log2e/256)
#define ESC2 1.127105500694502e-2f

// ---------------------------------------------------------------------------
// Static scratch
// ---------------------------------------------------------------------------
__device__ __align__(16) __half g_reph[(size_t)NROWS * D];   // 8 MB fp16
__device__ double g_acc[2];        // [0] = S_offdiag (x2), [1] = nominator
__device__ unsigned int g_done;    // CTA arrival counter (self-resetting)

// ---------------------------------------------------------------------------
// Helpers
// ---------------------------------------------------------------------------
__device__ __forceinline__ uint32_t smem_u32(const void* p) {
    uint32_t a;
    asm("{ .reg .u64 t; cvta.to.shared.u64 t, %1; cvt.u32.u64 %0, t; }"
        : "=r"(a) : "l"(p));
    return a;
}

#define MBAR_INIT(addr, cnt) \
    asm volatile("mbarrier.init.shared.b64 [%0], %1;" :: "r"(addr), "r"(cnt) : "memory")

#define MBAR_ARRIVE(addr) \
    asm volatile("mbarrier.arrive.shared.b64 _, [%0];" :: "r"(addr) : "memory")

#define MBAR_WAIT(addr, par) do {                                              \
    uint32_t _m = (addr), _p = (par), _d;                                      \
    asm volatile("{\n\t.reg .pred p;\n\t"                                      \
        "mbarrier.try_wait.parity.acquire.cta.shared::cta.b64 p, [%1], %2;\n\t"\
        "selp.b32 %0, 1, 0, p;\n\t}"                                           \
        : "=r"(_d) : "r"(_m), "r"(_p) : "memory");                             \
    if (!_d) {                                                                 \
        asm volatile("{\n\t.reg .pred P1;\n\t"                                 \
            "W%=:\n\t"                                                         \
            "mbarrier.try_wait.parity.acquire.cta.shared::cta.b64 P1, [%0], %1, 0x989680;\n\t" \
            "@P1 bra.uni DN%=;\n\tbra.uni W%=;\n\tDN%=:\n\t}"                  \
            :: "r"(_m), "r"(_p) : "memory");                                   \
    }                                                                          \
} while (0)

// TMA: arm barrier for 48KB; A = 1 box (128 rows), B = 2 boxes (256 rows)
__device__ __forceinline__ void tma_issue(uint32_t bar, uint32_t dstA, uint32_t dstB,
                                          const CUtensorMap* tm,
                                          int kx, int rowA, int rowB) {
    asm volatile("mbarrier.arrive.expect_tx.shared.b64 _, [%0], %1;"
                 :: "r"(bar), "r"(49152u) : "memory");
    asm volatile("cp.async.bulk.tensor.2d.shared::cta.global.tile.mbarrier::complete_tx::bytes "
                 "[%0], [%1, {%2, %3}], [%4];"
                 :: "r"(dstA), "l"(tm), "r"(kx), "r"(rowA), "r"(bar) : "memory");
    asm volatile("cp.async.bulk.tensor.2d.shared::cta.global.tile.mbarrier::complete_tx::bytes "
                 "[%0], [%1, {%2, %3}], [%4];"
                 :: "r"(dstB), "l"(tm), "r"(kx), "r"(rowB), "r"(bar) : "memory");
    asm volatile("cp.async.bulk.tensor.2d.shared::cta.global.tile.mbarrier::complete_tx::bytes "
                 "[%0], [%1, {%2, %3}], [%4];"
                 :: "r"(dstB + (uint32_t)A_B), "l"(tm),
                    "r"(kx), "r"(rowB + TM_CTA), "r"(bar) : "memory");
}

__device__ __forceinline__ void ldmx4(uint32_t& r0, uint32_t& r1,
                                      uint32_t& r2, uint32_t& r3, uint32_t a) {
    asm volatile("ldmatrix.sync.aligned.m8n8.x4.shared.b16 {%0,%1,%2,%3}, [%4];"
                 : "=r"(r0), "=r"(r1), "=r"(r2), "=r"(r3) : "r"(a));
}

// fp16 in, fp16 ACC: 2 packed regs per frag -> 64x64 warp tile in 64 regs.
__device__ __forceinline__ void mma16816h(uint32_t* c, const uint32_t* a,
                                          const uint32_t* b) {
    asm volatile(
        "mma.sync.aligned.m16n8k16.row.col.f16.f16.f16.f16 "
        "{%0,%1}, {%2,%3,%4,%5}, {%6,%7}, {%0,%1};"
        : "+r"(c[0]), "+r"(c[1])
        : "r"(a[0]), "r"(a[1]), "r"(a[2]), "r"(a[3]), "r"(b[0]), "r"(b[1]));
}

// exp(2*dot) from scaled f16-acc value via MUFU.EX2.
__device__ __forceinline__ float exp2dot_mufu(float acc) {
    float y;
    asm("ex2.approx.f32 %0, %1;" : "=f"(y) : "f"(acc * ESC2));
    return y;
}

// Decode linear tile index -> (bi of 128 rows, cb of 256 cols), pair scheme.
__device__ __forceinline__ void decode_tile(int t, int& bi, int& cb) {
    int p = (int)((65.0f - sqrtf(4225.0f - 4.0f * (float)t)) * 0.5f);
    if (p > 31) p = 31;
    while (p * (65 - p) > t) p--;
    while ((p + 1) * (64 - p) <= t) p++;
    int rem = t - p * (65 - p);
    int cnt = 32 - p;
    bi = 2 * p + (rem >= cnt ? 1 : 0);
    cb = p + (rem >= cnt ? rem - cnt : rem);
}

// ---------------------------------------------------------------------------
// K1: L2-normalize rows of [emb_i; emb_j], scale x16, -> fp16 g_reph.
// One block per row. Block 0 also zeroes the accumulators.
// ---------------------------------------------------------------------------
__global__ void normalize_kernel(const float* __restrict__ a,
                                 const float* __restrict__ b) {
    int row = blockIdx.x;
    int tid = threadIdx.x;  // 128
    if (row == 0 && tid == 0) { g_acc[0] = 0.0; g_acc[1] = 0.0; }

    const float* src = (row < HALF) ? (a + (size_t)row * D)
                                    : (b + (size_t)(row - HALF) * D);

    float4 v = reinterpret_cast<const float4*>(src)[tid];
    float ss = v.x * v.x + v.y * v.y + v.z * v.z + v.w * v.w;

    #pragma unroll
    for (int o = 16; o > 0; o >>= 1)
        ss += __shfl_xor_sync(0xFFFFFFFFu, ss, o);

    __shared__ float ws[4];
    int wid = tid >> 5, lane = tid & 31;
    if (lane == 0) ws[wid] = ss;
    __syncthreads();

    float total = ws[0] + ws[1] + ws[2] + ws[3];
    float s = rsqrtf(fmaxf(total, 1e-24f)) * 16.0f;  // normalize + f16 scale

    __half2 lo = __floats2half2_rn(v.x * s, v.y * s);
    __half2 hi = __floats2half2_rn(v.z * s, v.w * s);
    uint2 pk;
    pk.x = *reinterpret_cast<uint32_t*>(&lo);
    pk.y = *reinterpret_cast<uint32_t*>(&hi);
    reinterpret_cast<uint2*>(g_reph + (size_t)row * D)[tid] = pk;
}

// ---------------------------------------------------------------------------
// K2: PERSISTENT fp16 mma.sync GEMM, 128x256 CTA tiles, 8 warps of 64x64
// (1.0 smem-wavefront/MMA, fp16 acc keeps occ 2). 2-stage TMA ring across
// tile boundaries, barrier-free mainloop, per-thread sums, MUFU exp.
// ---------------------------------------------------------------------------
__global__ __launch_bounds__(NT, 2)
void gemm_exp_kernel(float* __restrict__ out,
                     const __grid_constant__ CUtensorMap tmap) {
    extern __shared__ char smraw[];
    uint32_t raw  = smem_u32(smraw);
    uint32_t base = (raw + 1023u) & ~1023u;   // 1024-align (SW128 atom span)
    uint32_t stg  = base + 1024;
    // header: full[s]@base+8s, empty[s]@base+32+8s, wred@base+128

    const int tid    = threadIdx.x;
    const int wid    = tid >> 5;
    const int lane   = tid & 31;
    const int warp_m = wid & 1;      // 2 warps down M (64 rows each)
    const int warp_n = wid >> 1;     // 4 warps across N (64 cols each)
    const int bid    = blockIdx.x;

    const int nt   = (NTILES - bid + GRID - 1) / GRID;   // tiles for this CTA
    const int Ltot = nt * NCHUNK;

    if (tid == 0) {
        #pragma unroll
        for (int s = 0; s < NSTAGE; s++) {
            MBAR_INIT(base + 8 * s, 1);        // full[s]
            MBAR_INIT(base + 32 + 8 * s, 8);   // empty[s]
        }
    }
    __syncthreads();

    // Tile bookkeeping
    int biC, cbC, biN = 0, cbN = 0;
    decode_tile(bid, biC, cbC);
    if (nt > 1) decode_tile(bid + GRID, biN, cbN);

    // Prologue: arm chunks 0,1 into slots 0,1
    if (tid == 0) {
        #pragma unroll
        for (int s = 0; s < NSTAGE; s++) {
            uint32_t sl = stg + (uint32_t)s * SLOT_B;
            tma_issue(base + 8 * s, sl, sl + A_B, &tmap,
                      s * KC, biC * TM_CTA, cbC * TN_CTA);
        }
    }

    // Per-lane ldmatrix address components (SW128 swizzle-aware)
    const int a_row = lane & 15;
    const int a_hi  = lane >> 4;
    const int a_sw  = a_row & 7;
    const int b_n   = ((lane >> 4) << 3) + (lane & 7);
    const int b_hi  = (lane >> 3) & 1;
    const int b_sw  = b_n & 7;
    const int grp   = lane >> 2;
    const int tig   = lane & 3;

    float sumT = 0.0f, nomT = 0.0f;
    int L = 0, slot = 0, par = 0;

    #pragma unroll 1
    for (int ti = 0; ti < nt; ti++) {
        uint32_t acc[4][8][2];   // fp16x2 accumulators, 64x64 warp tile
        #pragma unroll
        for (int mf = 0; mf < 4; mf++)
            #pragma unroll
            for (int nf = 0; nf < 8; nf++) {
                acc[mf][nf][0] = 0u;
                acc[mf][nf][1] = 0u;
            }

        #pragma unroll 1
        for (int j = 0; j < NCHUNK; j++) {
            MBAR_WAIT(base + 8 * slot, par);

            uint32_t sA = stg + (uint32_t)slot * SLOT_B;
            uint32_t sB = sA + A_B;

            #pragma unroll
            for (int ks = 0; ks < 4; ks++) {
                uint32_t afr[4][4];
                #pragma unroll
                for (int mf = 0; mf < 4; mf++) {
                    int grow = warp_m * 64 + mf * 16 + a_row;
                    uint32_t ca = (uint32_t)((2 * ks + a_hi) ^ a_sw);
                    ldmx4(afr[mf][0], afr[mf][1], afr[mf][2], afr[mf][3],
                          sA + grow * 128 + ca * 16);
                }
                uint32_t bfr[8][2];
                #pragma unroll
                for (int np = 0; np < 4; np++) {
                    int gn = warp_n * 64 + np * 16 + b_n;
                    uint32_t cbx = (uint32_t)((2 * ks + b_hi) ^ b_sw);
                    uint32_t r0, r1, r2, r3;
                    ldmx4(r0, r1, r2, r3, sB + gn * 128 + cbx * 16);
                    bfr[2 * np][0] = r0;     bfr[2 * np][1] = r1;
                    bfr[2 * np + 1][0] = r2; bfr[2 * np + 1][1] = r3;
                }
                #pragma unroll
                for (int mf = 0; mf < 4; mf++)
                    #pragma unroll
                    for (int nf = 0; nf < 8; nf++)
                        mma16816h(acc[mf][nf], afr[mf], bfr[nf]);
            }

            // Continuous slot recycle: producer warp L&7 re-arms with chunk
            // L+2 (possibly next tile's) after all 8 warps release the slot.
            int Ln = L + NSTAGE;
            if (Ln < Ltot && lane == 0) {
                MBAR_ARRIVE(base + 32 + 8 * slot);
                if (wid == (L & 7)) {
                    MBAR_WAIT(base + 32 + 8 * slot, par);
                    int koff = (Ln % NCHUNK) * KC;
                    bool nx  = (Ln / NCHUNK) != ti;
                    int rA   = (nx ? biN : biC) * TM_CTA;
                    int rB   = (nx ? cbN : cbC) * TN_CTA;
                    tma_issue(base + 8 * slot, sA, sB, &tmap, koff, rA, rB);
                }
            }

            L++;
            if (++slot == NSTAGE) { slot = 0; par ^= 1; }
        }

        // Tile epilogue — no sync/atomics; unpack f16x2, MUFU exp, masks.
        const int mbase = biC * TM_CTA + warp_m * 64;
        const int nbase = cbC * TN_CTA + warp_n * 64;
        #pragma unroll
        for (int mf = 0; mf < 4; mf++) {
            #pragma unroll
            for (int nf = 0; nf < 8; nf++) {
                int m0 = mbase + mf * 16 + grp;
                int n0 = nbase + nf * 8 + tig * 2;
                #pragma unroll
                for (int h = 0; h < 2; h++) {           // c0: row m0, c1: m0+8
                    int mm = m0 + h * 8;
                    __half2 hv = *reinterpret_cast<__half2*>(&acc[mf][nf][h]);
                    float2 f2 = __half22float2(hv);
                    #pragma unroll
                    for (int e = 0; e < 2; e++) {
                        int nn = n0 + e;
                        float ex = exp2dot_mufu(e ? f2.y : f2.x);
                        int dnm = nn - mm;
                        if (dnm > 0) sumT += ex;
                        if ((dnm == 2048) | (dnm == 4096) | (dnm == 6144))
                            nomT += ex;
                    }
                }
            }
        }

        biC = biN; cbC = cbN;
        if (ti + 2 < nt) decode_tile(bid + (ti + 2) * GRID, biN, cbN);
    }

    // Final reduction: shfl in-warp, 8 partials in header smem, warp 0 ends.
    #pragma unroll
    for (int o = 16; o > 0; o >>= 1) {
        sumT += __shfl_xor_sync(0xFFFFFFFFu, sumT, o);
        nomT += __shfl_xor_sync(0xFFFFFFFFu, nomT, o);
    }
    uint32_t wred = base + 128;
    if (lane == 0)
        asm volatile("st.shared.v2.f32 [%0], {%1, %2};"
                     :: "r"(wred + 8u * wid), "f"(sumT), "f"(nomT) : "memory");
    __syncthreads();
    if (wid == 0) {
        float2 v2 = make_float2(0.0f, 0.0f);
        if (lane < 8)
            asm volatile("ld.shared.v2.f32 {%0, %1}, [%2];"
                         : "=f"(v2.x), "=f"(v2.y) : "r"(wred + 8u * lane));
        #pragma unroll
        for (int o = 4; o > 0; o >>= 1) {
            v2.x += __shfl_xor_sync(0xFFFFFFFFu, v2.x, o);
            v2.y += __shfl_xor_sync(0xFFFFFFFFu, v2.y, o);
        }
        if (lane == 0) {
            atomicAdd(&g_acc[0], 2.0 * (double)v2.x);   // mirror lower triangle
            if (v2.y != 0.0f) atomicAdd(&g_acc[1], 2.0 * (double)v2.y);

            // Last-CTA finalize
            __threadfence();
            unsigned int t = atomicAdd(&g_done, 1u);
            if (t == GRID - 1) {
                __threadfence();
                double nomv = g_acc[1];
                double den  = g_acc[0] - nomv;
                out[0] = (float)(-log(nomv / den) / (double)NROWS);
                g_done = 0;   // reset for next graph replay
            }
        }
    }
}

// ---------------------------------------------------------------------------
// Entry point
// ---------------------------------------------------------------------------
typedef CUresult (*EncodeTiledFn)(
    CUtensorMap*, CUtensorMapDataType, cuuint32_t, void*,
    const cuuint64_t*, const cuuint64_t*, const cuuint32_t*, const cuuint32_t*,
    CUtensorMapInterleave, CUtensorMapSwizzle, CUtensorMapL2promotion,
    CUtensorMapFloatOOBfill);

extern "C" void kernel_launch(void* const* d_in, const int* in_sizes, int n_in,
                              void* d_out, int out_size) {
    const float* emb_i = (const float*)d_in[0];
    const float* emb_j = (const float*)d_in[1];
    float* out = (float*)d_out;

    void* reph_ptr = nullptr;
    cudaGetSymbolAddress(&reph_ptr, g_reph);

    EncodeTiledFn encode = nullptr;
    cudaDriverEntryPointQueryResult qres;
    cudaGetDriverEntryPoint("cuTensorMapEncodeTiled", (void**)&encode,
                            cudaEnableDefault, &qres);

    CUtensorMap tmap;
    cuuint64_t gdim[2]    = {(cuuint64_t)D, (cuuint64_t)NROWS};
    cuuint64_t gstride[1] = {(cuuint64_t)D * 2};            // row pitch bytes
    cuuint32_t box[2]     = {KC, TM_CTA};                   // 64 x 128 elems
    cuuint32_t estride[2] = {1, 1};
    encode(&tmap, CU_TENSOR_MAP_DATA_TYPE_FLOAT16, 2, reph_ptr,
           gdim, gstride, box, estride,
           CU_TENSOR_MAP_INTERLEAVE_NONE, CU_TENSOR_MAP_SWIZZLE_128B,
           CU_TENSOR_MAP_L2_PROMOTION_L2_128B,
           CU_TENSOR_MAP_FLOAT_OOB_FILL_NONE);

    cudaFuncSetAttribute(gemm_exp_kernel,
                         cudaFuncAttributeMaxDynamicSharedMemorySize, SMEM_DYN);

    normalize_kernel<<<NROWS, 128>>>(emb_i, emb_j);
    gemm_exp_kernel<<<GRID, NT, SMEM_DYN>>>(out, tmap);
}

// round 15
// speedup vs baseline: 1.6929x; 1.6929x over previous
#include <cuda_runtime.h>
#include <cuda.h>
#include <cuda_bf16.h>
#include <math.h>
#include <cstdint>

// ---------------------------------------------------------------------------
// Problem constants
// ---------------------------------------------------------------------------
#define NROWS 8192       // 4B rows in rep
#define HALF  4096       // rows per input
#define D     512        // embedding dim

// GEMM config: 128x128 CTA tile, 8 warps of 64x32, K chunked by 64 bf16
#define TILE    128
#define KC      64
#define NCHUNK  (D / KC)           // 8
#define NT      256
#define NSTAGE  3
#define OP_B    (TILE * KC * 2)    // 16384 B per operand per stage
#define SLOT_B  (2 * OP_B)         // A + B per stage = 32 KB
#define SMEM_DYN (2048 + NSTAGE * SLOT_B)  // hdr/align + 3 stages = 100352 B

#define NTILES  2080               // 64*65/2 upper-triangular 128x128 tiles
#define GRID    296                // persistent CTAs, 2 per SM (all resident)

// ---------------------------------------------------------------------------
// Static scratch
// ---------------------------------------------------------------------------
__device__ __align__(16) __nv_bfloat16 g_repb[(size_t)NROWS * D];  // 8 MB
__device__ double g_acc[2];        // [0] = S_offdiag (x2), [1] = nominator
__device__ unsigned int g_done;    // CTA arrival counter (self-resetting)
__device__ unsigned int g_sync;    // grid barrier counter (self-resetting)

// ---------------------------------------------------------------------------
// Helpers
// ---------------------------------------------------------------------------
__device__ __forceinline__ uint32_t smem_u32(const void* p) {
    uint32_t a;
    asm("{ .reg .u64 t; cvta.to.shared.u64 t, %1; cvt.u32.u64 %0, t; }"
        : "=r"(a) : "l"(p));
    return a;
}

#define MBAR_INIT(addr, cnt) \
    asm volatile("mbarrier.init.shared.b64 [%0], %1;" :: "r"(addr), "r"(cnt) : "memory")

#define MBAR_ARRIVE(addr) \
    asm volatile("mbarrier.arrive.shared.b64 _, [%0];" :: "r"(addr) : "memory")

#define MBAR_WAIT(addr, par) do {                                              \
    uint32_t _m = (addr), _p = (par), _d;                                      \
    asm volatile("{\n\t.reg .pred p;\n\t"                                      \
        "mbarrier.try_wait.parity.acquire.cta.shared::cta.b64 p, [%1], %2;\n\t"\
        "selp.b32 %0, 1, 0, p;\n\t}"                                           \
        : "=r"(_d) : "r"(_m), "r"(_p) : "memory");                             \
    if (!_d) {                                                                 \
        asm volatile("{\n\t.reg .pred P1;\n\t"                                 \
            "W%=:\n\t"                                                         \
            "mbarrier.try_wait.parity.acquire.cta.shared::cta.b64 P1, [%0], %1, 0x989680;\n\t" \
            "@P1 bra.uni DN%=;\n\tbra.uni W%=;\n\tDN%=:\n\t}"                  \
            :: "r"(_m), "r"(_p) : "memory");                                   \
    }                                                                          \
} while (0)

// TMA: arm barrier for 32KB and issue A+B box loads (64 x 128 bf16, SW128)
__device__ __forceinline__ void tma_issue(uint32_t bar, uint32_t dstA, uint32_t dstB,
                                          const CUtensorMap* tm,
                                          int kx, int rowA, int rowB) {
    asm volatile("mbarrier.arrive.expect_tx.shared.b64 _, [%0], %1;"
                 :: "r"(bar), "r"(32768u) : "memory");
    asm volatile("cp.async.bulk.tensor.2d.shared::cta.global.tile.mbarrier::complete_tx::bytes "
                 "[%0], [%1, {%2, %3}], [%4];"
                 :: "r"(dstA), "l"(tm), "r"(kx), "r"(rowA), "r"(bar) : "memory");
    asm volatile("cp.async.bulk.tensor.2d.shared::cta.global.tile.mbarrier::complete_tx::bytes "
                 "[%0], [%1, {%2, %3}], [%4];"
                 :: "r"(dstB), "l"(tm), "r"(kx), "r"(rowB), "r"(bar) : "memory");
}

__device__ __forceinline__ void ldmx4(uint32_t& r0, uint32_t& r1,
                                      uint32_t& r2, uint32_t& r3, uint32_t a) {
    asm volatile("ldmatrix.sync.aligned.m8n8.x4.shared.b16 {%0,%1,%2,%3}, [%4];"
                 : "=r"(r0), "=r"(r1), "=r"(r2), "=r"(r3) : "r"(a));
}

__device__ __forceinline__ void mma16816(float* c, const uint32_t* a,
                                         const uint32_t* b) {
    asm volatile(
        "mma.sync.aligned.m16n8k16.row.col.f32.bf16.bf16.f32 "
        "{%0,%1,%2,%3}, {%4,%5,%6,%7}, {%8,%9}, {%0,%1,%2,%3};"
        : "+f"(c[0]), "+f"(c[1]), "+f"(c[2]), "+f"(c[3])
        : "r"(a[0]), "r"(a[1]), "r"(a[2]), "r"(a[3]), "r"(b[0]), "r"(b[1]));
}

// exp(2x) = 2^(x * 2*log2(e)) via MUFU.EX2 — 2 instructions, idle pipe.
__device__ __forceinline__ float exp2dot_mufu(float x) {
    float y;
    asm("ex2.approx.f32 %0, %1;" : "=f"(y) : "f"(x * 2.88539008177792681f));
    return y;
}

// Decode linear upper-triangular tile index -> (bi, bj), bj >= bi, 64 rows.
__device__ __forceinline__ void decode_tile(int t, int& bi, int& bj) {
    int b = (int)((129.0f - sqrtf(16641.0f - 8.0f * (float)t)) * 0.5f);
    if (b > 63) b = 63;
    while (b * (129 - b) / 2 > t) b--;
    while ((b + 1) * (129 - (b + 1)) / 2 <= t) b++;
    bi = b;
    bj = b + (t - b * (129 - b) / 2);
}

// ---------------------------------------------------------------------------
// Single PERSISTENT kernel: phase 1 normalizes rows into bf16 g_repb,
// grid-barrier, phase 2 runs the fused GEMM+exp over 2080 tiles.
// ---------------------------------------------------------------------------
__global__ __launch_bounds__(NT, 2)
void fused_kernel(float* __restrict__ out,
                  const __grid_constant__ CUtensorMap tmap,
                  const float* __restrict__ ea,
                  const float* __restrict__ eb) {
    extern __shared__ char smraw[];
    uint32_t raw  = smem_u32(smraw);
    uint32_t base = (raw + 1023u) & ~1023u;   // 1024-align (SW128 atom span)
    uint32_t stg  = base + 1024;
    char*    hdr  = smraw + (base - raw);
    // header: full[s]@base+8s, empty[s]@base+32+8s, wred@base+128, ws@base+256

    const int tid    = threadIdx.x;
    const int wid    = tid >> 5;
    const int lane   = tid & 31;
    const int warp_m = wid & 1;
    const int warp_n = wid >> 1;
    const int bid    = blockIdx.x;

    if (tid == 0) {
        #pragma unroll
        for (int s = 0; s < NSTAGE; s++) {
            MBAR_INIT(base + 8 * s, 1);        // full[s]
            MBAR_INIT(base + 32 + 8 * s, 8);   // empty[s]
        }
        if (bid == 0) { g_acc[0] = 0.0; g_acc[1] = 0.0; }
    }
    __syncthreads();

    // ---------------- Phase 1: normalize (2 rows per CTA-iteration) --------
    {
        const int half8 = tid >> 7;         // 0/1: which row of the pair
        const int t128  = tid & 127;
        const int nwid  = t128 >> 5;
        const int nlane = t128 & 31;
        float* ws = reinterpret_cast<float*>(hdr + 256);

        for (int pr = bid; pr < HALF; pr += GRID) {
            int row = 2 * pr + half8;
            const float* src = (row < HALF) ? (ea + (size_t)row * D)
                                            : (eb + (size_t)(row - HALF) * D);
            float4 v = reinterpret_cast<const float4*>(src)[t128];
            float ss = v.x * v.x + v.y * v.y + v.z * v.z + v.w * v.w;
            #pragma unroll
            for (int o = 16; o > 0; o >>= 1)
                ss += __shfl_xor_sync(0xFFFFFFFFu, ss, o);
            if (nlane == 0) ws[half8 * 4 + nwid] = ss;
            __syncthreads();
            float total = ws[half8 * 4 + 0] + ws[half8 * 4 + 1]
                        + ws[half8 * 4 + 2] + ws[half8 * 4 + 3];
            float inv = rsqrtf(fmaxf(total, 1e-24f));   // x / max(norm,1e-12)
            __nv_bfloat162 lo = __floats2bfloat162_rn(v.x * inv, v.y * inv);
            __nv_bfloat162 hi = __floats2bfloat162_rn(v.z * inv, v.w * inv);
            uint2 pk;
            pk.x = *reinterpret_cast<uint32_t*>(&lo);
            pk.y = *reinterpret_cast<uint32_t*>(&hi);
            reinterpret_cast<uint2*>(g_repb + (size_t)row * D)[t128] = pk;
            __syncthreads();
        }
    }

    // Grid barrier: all 296 CTAs resident (2/SM) -> spin is deadlock-free.
    __threadfence();
    if (tid == 0) {
        atomicAdd(&g_sync, 1u);
        while (*((volatile unsigned int*)&g_sync) < GRID) {}
    }
    __syncthreads();

    // ---------------- Phase 2: persistent GEMM + exp reduction -------------
    const int nt   = (NTILES - bid + GRID - 1) / GRID;
    const int Ltot = nt * NCHUNK;

    int biC, bjC, biN = 0, bjN = 0;
    decode_tile(bid, biC, bjC);
    if (nt > 1) decode_tile(bid + GRID, biN, bjN);

    if (tid == 0) {
        #pragma unroll
        for (int s = 0; s < NSTAGE; s++) {
            uint32_t sl = stg + (uint32_t)s * SLOT_B;
            tma_issue(base + 8 * s, sl, sl + OP_B, &tmap,
                      s * KC, biC * TILE, bjC * TILE);
        }
    }

    // Per-lane ldmatrix address components (SW128 swizzle-aware)
    const int a_row = lane & 15;
    const int a_hi  = lane >> 4;
    const int a_sw  = a_row & 7;
    const int b_n   = ((lane >> 4) << 3) + (lane & 7);
    const int b_hi  = (lane >> 3) & 1;
    const int b_sw  = b_n & 7;
    const int grp   = lane >> 2;
    const int tig   = lane & 3;

    const int a_base = warp_m * 64 + a_row;     // + mf*16
    const int b_base = warp_n * 32 + b_n;       // + np*16

    float sumT = 0.0f, nomT = 0.0f;
    int L = 0, slot = 0, par = 0;

    // Fragment load macros (double-buffered A over mf, B over ks)
    #define LDA(buf, ksq, mfq) \
        ldmx4((buf)[0], (buf)[1], (buf)[2], (buf)[3], \
              sA + (uint32_t)((a_base + (mfq) * 16) * 128) \
                 + (uint32_t)(((2 * (ksq) + a_hi) ^ a_sw) << 4))
    #define LDB(buf, ksq) do { \
        _Pragma("unroll") \
        for (int np = 0; np < 2; np++) { \
            uint32_t r0, r1, r2, r3; \
            ldmx4(r0, r1, r2, r3, \
                  sB + (uint32_t)((b_base + np * 16) * 128) \
                     + (uint32_t)(((2 * (ksq) + b_hi) ^ b_sw) << 4)); \
            (buf)[2 * np][0] = r0;     (buf)[2 * np][1] = r1; \
            (buf)[2 * np + 1][0] = r2; (buf)[2 * np + 1][1] = r3; \
        } \
    } while (0)

    #pragma unroll 1
    for (int ti = 0; ti < nt; ti++) {
        float acc[4][4][4];
        #pragma unroll
        for (int mf = 0; mf < 4; mf++)
            #pragma unroll
            for (int nf = 0; nf < 4; nf++)
                #pragma unroll
                for (int e = 0; e < 4; e++)
                    acc[mf][nf][e] = 0.0f;

        #pragma unroll 1
        for (int j = 0; j < NCHUNK; j++) {
            MBAR_WAIT(base + 8 * slot, par);

            uint32_t sA = stg + (uint32_t)slot * SLOT_B;
            uint32_t sB = sA + OP_B;

            uint32_t bfr[2][4][2];   // B double-buffered over ks
            uint32_t afr[2][4];      // A double-buffered over mf

            LDB(bfr[0], 0);
            LDA(afr[0], 0, 0);

            #pragma unroll
            for (int ks = 0; ks < 4; ks++) {
                const int cb = ks & 1;
                #pragma unroll
                for (int mf = 0; mf < 4; mf++) {
                    const int ca = mf & 1;
                    // Prefetch one buffer ahead (hidden behind 4 MMAs)
                    if (mf == 0 && ks < 3) LDB(bfr[cb ^ 1], ks + 1);
                    if (mf < 3)            LDA(afr[ca ^ 1], ks, mf + 1);
                    else if (ks < 3)       LDA(afr[ca ^ 1], ks + 1, 0);
                    #pragma unroll
                    for (int nf = 0; nf < 4; nf++)
                        mma16816(acc[mf][nf], afr[ca], bfr[cb][nf]);
                }
            }

            // Continuous slot recycle (barrier-free)
            int Ln = L + NSTAGE;
            if (Ln < Ltot && lane == 0) {
                MBAR_ARRIVE(base + 32 + 8 * slot);
                if (wid == (L & 7)) {
                    MBAR_WAIT(base + 32 + 8 * slot, par);
                    int koff = (Ln % NCHUNK) * KC;
                    bool nx  = (Ln / NCHUNK) != ti;
                    int rA   = (nx ? biN : biC) * TILE;
                    int rB   = (nx ? bjN : bjC) * TILE;
                    tma_issue(base + 8 * slot, sA, sB, &tmap, koff, rA, rB);
                }
            }

            L++;
            if (++slot == NSTAGE) { slot = 0; par ^= 1; }
        }

        // Tile epilogue — register accumulation, MUFU exp, masked sums.
        const bool diag = (biC == bjC);
        const int  dbj  = bjC - biC;
        const bool nomt = (dbj == 16) | (dbj == 32) | (dbj == 48);
        #pragma unroll
        for (int mf = 0; mf < 4; mf++) {
            #pragma unroll
            for (int nf = 0; nf < 4; nf++) {
                int m0 = warp_m * 64 + mf * 16 + grp;
                int n0 = warp_n * 32 + nf * 8 + tig * 2;
                #pragma unroll
                for (int e = 0; e < 4; e++) {
                    int mm = m0 + (e >> 1) * 8;
                    int nn = n0 + (e & 1);
                    float ex = exp2dot_mufu(acc[mf][nf][e]);
                    if (!diag || nn > mm) sumT += ex;
                    if (nomt & (nn == mm)) nomT += ex;
                }
            }
        }

        biC = biN; bjC = bjN;
        if (ti + 2 < nt) decode_tile(bid + (ti + 2) * GRID, biN, bjN);
    }
    #undef LDA
    #undef LDB

    // Final reduction: shfl in-warp, 8 partials in header smem, warp 0 ends.
    #pragma unroll
    for (int o = 16; o > 0; o >>= 1) {
        sumT += __shfl_xor_sync(0xFFFFFFFFu, sumT, o);
        nomT += __shfl_xor_sync(0xFFFFFFFFu, nomT, o);
    }
    uint32_t wred = base + 128;
    if (lane == 0)
        asm volatile("st.shared.v2.f32 [%0], {%1, %2};"
                     :: "r"(wred + 8u * wid), "f"(sumT), "f"(nomT) : "memory");
    __syncthreads();
    if (wid == 0) {
        float2 v2 = make_float2(0.0f, 0.0f);
        if (lane < 8)
            asm volatile("ld.shared.v2.f32 {%0, %1}, [%2];"
                         : "=f"(v2.x), "=f"(v2.y) : "r"(wred + 8u * lane));
        #pragma unroll
        for (int o = 4; o > 0; o >>= 1) {
            v2.x += __shfl_xor_sync(0xFFFFFFFFu, v2.x, o);
            v2.y += __shfl_xor_sync(0xFFFFFFFFu, v2.y, o);
        }
        if (lane == 0) {
            atomicAdd(&g_acc[0], 2.0 * (double)v2.x);   // mirror lower triangle
            if (v2.y != 0.0f) atomicAdd(&g_acc[1], 2.0 * (double)v2.y);

            // Last-CTA finalize (+ reset counters for graph replay)
            __threadfence();
            unsigned int t = atomicAdd(&g_done, 1u);
            if (t == GRID - 1) {
                __threadfence();
                double nomv = g_acc[1];
                double den  = g_acc[0] - nomv;
                out[0] = (float)(-log(nomv / den) / (double)NROWS);
                g_done = 0;
                g_sync = 0;
            }
        }
    }
}

// ---------------------------------------------------------------------------
// Entry point
// ---------------------------------------------------------------------------
typedef CUresult (*EncodeTiledFn)(
    CUtensorMap*, CUtensorMapDataType, cuuint32_t, void*,
    const cuuint64_t*, const cuuint64_t*, const cuuint32_t*, const cuuint32_t*,
    CUtensorMapInterleave, CUtensorMapSwizzle, CUtensorMapL2promotion,
    CUtensorMapFloatOOBfill);

extern "C" void kernel_launch(void* const* d_in, const int* in_sizes, int n_in,
                              void* d_out, int out_size) {
    const float* emb_i = (const float*)d_in[0];
    const float* emb_j = (const float*)d_in[1];
    float* out = (float*)d_out;

    void* repb_ptr = nullptr;
    cudaGetSymbolAddress(&repb_ptr, g_repb);

    EncodeTiledFn encode = nullptr;
    cudaDriverEntryPointQueryResult qres;
    cudaGetDriverEntryPoint("cuTensorMapEncodeTiled", (void**)&encode,
                            cudaEnableDefault, &qres);

    CUtensorMap tmap;
    cuuint64_t gdim[2]    = {(cuuint64_t)D, (cuuint64_t)NROWS};
    cuuint64_t gstride[1] = {(cuuint64_t)D * 2};            // row pitch bytes
    cuuint32_t box[2]     = {KC, TILE};                     // 64 x 128 elems
    cuuint32_t estride[2] = {1, 1};
    encode(&tmap, CU_TENSOR_MAP_DATA_TYPE_BFLOAT16, 2, repb_ptr,
           gdim, gstride, box, estride,
           CU_TENSOR_MAP_INTERLEAVE_NONE, CU_TENSOR_MAP_SWIZZLE_128B,
           CU_TENSOR_MAP_L2_PROMOTION_L2_128B,
           CU_TENSOR_MAP_FLOAT_OOB_FILL_NONE);

    cudaFuncSetAttribute(fused_kernel,
                         cudaFuncAttributeMaxDynamicSharedMemorySize, SMEM_DYN);

    fused_kernel<<<GRID, NT, SMEM_DYN>>>(out, tmap, emb_i, emb_j);
}

// round 16
// speedup vs baseline: 1.8035x; 1.0653x over previous
#include <cuda_runtime.h>
#include <cuda.h>
#include <cuda_bf16.h>
#include <math.h>
#include <cstdint>

// ---------------------------------------------------------------------------
// Problem constants
// ---------------------------------------------------------------------------
#define NROWS 8192       // 4B rows in rep
#define HALF  4096       // rows per input
#define D     512        // embedding dim

// GEMM config: 128x128 CTA tile, 8 warps of 64x32, K chunked by 64 bf16
#define TILE    128
#define KC      64
#define NCHUNK  (D / KC)           // 8
#define NT      256
#define NSTAGE  3
#define OP_B    (TILE * KC * 2)    // 16384 B per operand per stage
#define SLOT_B  (2 * OP_B)         // A + B per stage = 32 KB
#define SMEM_DYN (2048 + NSTAGE * SLOT_B)  // hdr/align + 3 stages = 100352 B

#define NTILES  2080               // 64*65/2 upper-triangular 128x128 tiles
#define GRID    296                // persistent CTAs, 2 per SM

// ---------------------------------------------------------------------------
// Static scratch
// ---------------------------------------------------------------------------
__device__ __align__(16) __nv_bfloat16 g_repb[(size_t)NROWS * D];  // 8 MB
__device__ double g_acc[2];        // [0] = S_offdiag (x2), [1] = nominator
__device__ unsigned int g_done;    // CTA arrival counter (self-resetting)
__device__ unsigned int g_next;    // dynamic tile counter (self-resetting)

// ---------------------------------------------------------------------------
// Helpers
// ---------------------------------------------------------------------------
__device__ __forceinline__ uint32_t smem_u32(const void* p) {
    uint32_t a;
    asm("{ .reg .u64 t; cvta.to.shared.u64 t, %1; cvt.u32.u64 %0, t; }"
        : "=r"(a) : "l"(p));
    return a;
}

#define MBAR_INIT(addr, cnt) \
    asm volatile("mbarrier.init.shared.b64 [%0], %1;" :: "r"(addr), "r"(cnt) : "memory")

#define MBAR_ARRIVE(addr) \
    asm volatile("mbarrier.arrive.shared.b64 _, [%0];" :: "r"(addr) : "memory")

#define MBAR_WAIT(addr, par) do {                                              \
    uint32_t _m = (addr), _p = (par), _d;                                      \
    asm volatile("{\n\t.reg .pred p;\n\t"                                      \
        "mbarrier.try_wait.parity.acquire.cta.shared::cta.b64 p, [%1], %2;\n\t"\
        "selp.b32 %0, 1, 0, p;\n\t}"                                           \
        : "=r"(_d) : "r"(_m), "r"(_p) : "memory");                             \
    if (!_d) {                                                                 \
        asm volatile("{\n\t.reg .pred P1;\n\t"                                 \
            "W%=:\n\t"                                                         \
            "mbarrier.try_wait.parity.acquire.cta.shared::cta.b64 P1, [%0], %1, 0x989680;\n\t" \
            "@P1 bra.uni DN%=;\n\tbra.uni W%=;\n\tDN%=:\n\t}"                  \
            :: "r"(_m), "r"(_p) : "memory");                                   \
    }                                                                          \
} while (0)

// TMA: arm barrier for 32KB and issue A+B box loads (64 x 128 bf16, SW128)
__device__ __forceinline__ void tma_issue(uint32_t bar, uint32_t dstA, uint32_t dstB,
                                          const CUtensorMap* tm,
                                          int kx, int rowA, int rowB) {
    asm volatile("mbarrier.arrive.expect_tx.shared.b64 _, [%0], %1;"
                 :: "r"(bar), "r"(32768u) : "memory");
    asm volatile("cp.async.bulk.tensor.2d.shared::cta.global.tile.mbarrier::complete_tx::bytes "
                 "[%0], [%1, {%2, %3}], [%4];"
                 :: "r"(dstA), "l"(tm), "r"(kx), "r"(rowA), "r"(bar) : "memory");
    asm volatile("cp.async.bulk.tensor.2d.shared::cta.global.tile.mbarrier::complete_tx::bytes "
                 "[%0], [%1, {%2, %3}], [%4];"
                 :: "r"(dstB), "l"(tm), "r"(kx), "r"(rowB), "r"(bar) : "memory");
}

__device__ __forceinline__ void ldmx4(uint32_t& r0, uint32_t& r1,
                                      uint32_t& r2, uint32_t& r3, uint32_t a) {
    asm volatile("ldmatrix.sync.aligned.m8n8.x4.shared.b16 {%0,%1,%2,%3}, [%4];"
                 : "=r"(r0), "=r"(r1), "=r"(r2), "=r"(r3) : "r"(a));
}

__device__ __forceinline__ void mma16816(float* c, const uint32_t* a,
                                         const uint32_t* b) {
    asm volatile(
        "mma.sync.aligned.m16n8k16.row.col.f32.bf16.bf16.f32 "
        "{%0,%1,%2,%3}, {%4,%5,%6,%7}, {%8,%9}, {%0,%1,%2,%3};"
        : "+f"(c[0]), "+f"(c[1]), "+f"(c[2]), "+f"(c[3])
        : "r"(a[0]), "r"(a[1]), "r"(a[2]), "r"(a[3]), "r"(b[0]), "r"(b[1]));
}

// exp(2x) = 2^(x * 2*log2(e)) via MUFU.EX2 — 2 instructions, idle pipe.
__device__ __forceinline__ float exp2dot_mufu(float x) {
    float y;
    asm("ex2.approx.f32 %0, %1;" : "=f"(y) : "f"(x * 2.88539008177792681f));
    return y;
}

// Decode linear upper-triangular tile index -> (bi, bj), bj >= bi, 64 rows.
__device__ __forceinline__ void decode_tile(int t, int& bi, int& bj) {
    int b = (int)((129.0f - sqrtf(16641.0f - 8.0f * (float)t)) * 0.5f);
    if (b > 63) b = 63;
    while (b * (129 - b) / 2 > t) b--;
    while ((b + 1) * (129 - (b + 1)) / 2 <= t) b++;
    bi = b;
    bj = b + (t - b * (129 - b) / 2);
}

// ---------------------------------------------------------------------------
// K1: L2-normalize rows of [emb_i; emb_j] -> bf16 g_repb. One block per row.
// Block 0 also zeroes the accumulators.
// ---------------------------------------------------------------------------
__global__ void normalize_kernel(const float* __restrict__ a,
                                 const float* __restrict__ b) {
    int row = blockIdx.x;
    int tid = threadIdx.x;  // 128
    if (row == 0 && tid == 0) { g_acc[0] = 0.0; g_acc[1] = 0.0; }

    const float* src = (row < HALF) ? (a + (size_t)row * D)
                                    : (b + (size_t)(row - HALF) * D);

    float4 v = reinterpret_cast<const float4*>(src)[tid];
    float ss = v.x * v.x + v.y * v.y + v.z * v.z + v.w * v.w;

    #pragma unroll
    for (int o = 16; o > 0; o >>= 1)
        ss += __shfl_xor_sync(0xFFFFFFFFu, ss, o);

    __shared__ float ws[4];
    int wid = tid >> 5, lane = tid & 31;
    if (lane == 0) ws[wid] = ss;
    __syncthreads();

    float total = ws[0] + ws[1] + ws[2] + ws[3];
    float inv = rsqrtf(fmaxf(total, 1e-24f));  // == x / max(norm, 1e-12)

    __nv_bfloat162 lo = __floats2bfloat162_rn(v.x * inv, v.y * inv);
    __nv_bfloat162 hi = __floats2bfloat162_rn(v.z * inv, v.w * inv);
    uint2 pk;
    pk.x = *reinterpret_cast<uint32_t*>(&lo);
    pk.y = *reinterpret_cast<uint32_t*>(&hi);
    reinterpret_cast<uint2*>(g_repb + (size_t)row * D)[tid] = pk;
}

// ---------------------------------------------------------------------------
// K2: PERSISTENT bf16 mma.sync GEMM with DYNAMIC tile scheduling (atomic
// work-stealing removes the 8-straggler tail of the static schedule).
// Continuous 3-slot TMA ring across tile boundaries, barrier-free chunk
// loop, per-thread running sums, MUFU exp, last-CTA finalize.
// ---------------------------------------------------------------------------
__global__ __launch_bounds__(NT, 2)
void gemm_exp_kernel(float* __restrict__ out,
                     const __grid_constant__ CUtensorMap tmap) {
    extern __shared__ char smraw[];
    uint32_t raw  = smem_u32(smraw);
    uint32_t base = (raw + 1023u) & ~1023u;   // 1024-align (SW128 atom span)
    uint32_t stg  = base + 1024;
    // header: full[s]@base+8s, empty[s]@base+32+8s, wred@base+128, bc@base+192

    const int tid    = threadIdx.x;
    const int wid    = tid >> 5;
    const int lane   = tid & 31;
    const int warp_m = wid & 1;
    const int warp_n = wid >> 1;

    if (tid == 0) {
        #pragma unroll
        for (int s = 0; s < NSTAGE; s++) {
            MBAR_INIT(base + 8 * s, 1);        // full[s]
            MBAR_INIT(base + 32 + 8 * s, 8);   // empty[s]
        }
    }
    __syncthreads();

    // Fetch first two tiles (work-stealing)
    const uint32_t bc = base + 192;
    if (tid == 0) {
        uint32_t t0 = atomicAdd(&g_next, 2u);
        asm volatile("st.shared.v2.u32 [%0], {%1, %2};"
                     :: "r"(bc), "r"(t0), "r"(t0 + 1u) : "memory");
    }
    __syncthreads();
    int tC, tN;
    asm volatile("ld.shared.v2.u32 {%0, %1}, [%2];"
                 : "=r"(tC), "=r"(tN) : "r"(bc));

    int biC = 0, bjC = 0, biN = 0, bjN = 0;
    bool haveC = tC < NTILES;
    bool haveN = tN < NTILES;
    if (haveC) decode_tile(tC, biC, bjC);
    if (haveN) decode_tile(tN, biN, bjN);

    // Per-lane ldmatrix address components (SW128 swizzle-aware)
    const int a_row = lane & 15;
    const int a_hi  = lane >> 4;
    const int a_sw  = a_row & 7;
    const int b_n   = ((lane >> 4) << 3) + (lane & 7);
    const int b_hi  = (lane >> 3) & 1;
    const int b_sw  = b_n & 7;
    const int grp   = lane >> 2;
    const int tig   = lane & 3;

    float sumT = 0.0f, nomT = 0.0f;
    int L = 0, slot = 0, par = 0;

    if (haveC) {
        // Prologue: arm chunks 0..2 of the first tile
        if (tid == 0) {
            #pragma unroll
            for (int s = 0; s < NSTAGE; s++) {
                uint32_t sl = stg + (uint32_t)s * SLOT_B;
                tma_issue(base + 8 * s, sl, sl + OP_B, &tmap,
                          s * KC, biC * TILE, bjC * TILE);
            }
        }

        #pragma unroll 1
        while (true) {
            float acc[4][4][4];
            #pragma unroll
            for (int mf = 0; mf < 4; mf++)
                #pragma unroll
                for (int nf = 0; nf < 4; nf++)
                    #pragma unroll
                    for (int e = 0; e < 4; e++)
                        acc[mf][nf][e] = 0.0f;

            #pragma unroll 1
            for (int j = 0; j < NCHUNK; j++) {
                MBAR_WAIT(base + 8 * slot, par);

                uint32_t sA = stg + (uint32_t)slot * SLOT_B;
                uint32_t sB = sA + OP_B;

                #pragma unroll
                for (int ks = 0; ks < 4; ks++) {
                    uint32_t afr[4][4];
                    #pragma unroll
                    for (int mf = 0; mf < 4; mf++) {
                        int grow = warp_m * 64 + mf * 16 + a_row;
                        uint32_t ca = (uint32_t)((2 * ks + a_hi) ^ a_sw);
                        ldmx4(afr[mf][0], afr[mf][1], afr[mf][2], afr[mf][3],
                              sA + grow * 128 + ca * 16);
                    }
                    uint32_t bfr[4][2];
                    #pragma unroll
                    for (int np = 0; np < 2; np++) {
                        int gn = warp_n * 32 + np * 16 + b_n;
                        uint32_t cb = (uint32_t)((2 * ks + b_hi) ^ b_sw);
                        uint32_t r0, r1, r2, r3;
                        ldmx4(r0, r1, r2, r3, sB + gn * 128 + cb * 16);
                        bfr[2 * np][0] = r0;     bfr[2 * np][1] = r1;
                        bfr[2 * np + 1][0] = r2; bfr[2 * np + 1][1] = r3;
                    }
                    #pragma unroll
                    for (int mf = 0; mf < 4; mf++)
                        #pragma unroll
                        for (int nf = 0; nf < 4; nf++)
                            mma16816(acc[mf][nf], afr[mf], bfr[nf]);
                }

                // Slot recycle: re-arm chunk j+3 — of this tile for j<5,
                // of the NEXT tile for j>=5 (if one exists).
                bool rearm = (j < NCHUNK - NSTAGE) | haveN;
                if (rearm && lane == 0) {
                    MBAR_ARRIVE(base + 32 + 8 * slot);
                    if (wid == (L & 7)) {
                        MBAR_WAIT(base + 32 + 8 * slot, par);
                        int koff = ((j + NSTAGE) & (NCHUNK - 1)) * KC;
                        bool cur = (j < NCHUNK - NSTAGE);
                        int rA = (cur ? biC : biN) * TILE;
                        int rB = (cur ? bjC : bjN) * TILE;
                        tma_issue(base + 8 * slot, sA, sB, &tmap, koff, rA, rB);
                    }
                }

                L++;
                if (++slot == NSTAGE) { slot = 0; par ^= 1; }
            }

            // Tile epilogue — register accumulation, MUFU exp, masked sums.
            const bool diag = (biC == bjC);
            const int  dbj  = bjC - biC;
            const bool nomt = (dbj == 16) | (dbj == 32) | (dbj == 48);
            #pragma unroll
            for (int mf = 0; mf < 4; mf++) {
                #pragma unroll
                for (int nf = 0; nf < 4; nf++) {
                    int m0 = warp_m * 64 + mf * 16 + grp;
                    int n0 = warp_n * 32 + nf * 8 + tig * 2;
                    #pragma unroll
                    for (int e = 0; e < 4; e++) {
                        int mm = m0 + (e >> 1) * 8;
                        int nn = n0 + (e & 1);
                        float ex = exp2dot_mufu(acc[mf][nf][e]);
                        if (!diag || nn > mm) sumT += ex;
                        if (nomt & (nn == mm)) nomT += ex;
                    }
                }
            }

            if (!haveN) break;
            biC = biN; bjC = bjN;

            // Fetch the tile after next (broadcast via smem)
            __syncthreads();
            if (tid == 0) {
                uint32_t t = atomicAdd(&g_next, 1u);
                asm volatile("st.shared.u32 [%0], %1;"
                             :: "r"(bc), "r"(t) : "memory");
            }
            __syncthreads();
            asm volatile("ld.shared.u32 %0, [%1];" : "=r"(tN) : "r"(bc));
            haveN = tN < NTILES;
            if (haveN) decode_tile(tN, biN, bjN);
        }
    }

    // Final reduction: shfl in-warp, 8 partials in header smem, warp 0 ends.
    #pragma unroll
    for (int o = 16; o > 0; o >>= 1) {
        sumT += __shfl_xor_sync(0xFFFFFFFFu, sumT, o);
        nomT += __shfl_xor_sync(0xFFFFFFFFu, nomT, o);
    }
    uint32_t wred = base + 128;
    if (lane == 0)
        asm volatile("st.shared.v2.f32 [%0], {%1, %2};"
                     :: "r"(wred + 8u * wid), "f"(sumT), "f"(nomT) : "memory");
    __syncthreads();
    if (wid == 0) {
        float2 v2 = make_float2(0.0f, 0.0f);
        if (lane < 8)
            asm volatile("ld.shared.v2.f32 {%0, %1}, [%2];"
                         : "=f"(v2.x), "=f"(v2.y) : "r"(wred + 8u * lane));
        #pragma unroll
        for (int o = 4; o > 0; o >>= 1) {
            v2.x += __shfl_xor_sync(0xFFFFFFFFu, v2.x, o);
            v2.y += __shfl_xor_sync(0xFFFFFFFFu, v2.y, o);
        }
        if (lane == 0) {
            atomicAdd(&g_acc[0], 2.0 * (double)v2.x);   // mirror lower triangle
            if (v2.y != 0.0f) atomicAdd(&g_acc[1], 2.0 * (double)v2.y);

            // Last-CTA finalize (+ reset counters for graph replay)
            __threadfence();
            unsigned int t = atomicAdd(&g_done, 1u);
            if (t == GRID - 1) {
                __threadfence();
                double nomv = g_acc[1];
                double den  = g_acc[0] - nomv;
                out[0] = (float)(-log(nomv / den) / (double)NROWS);
                g_done = 0;
                g_next = 0;
            }
        }
    }
}

// ---------------------------------------------------------------------------
// Entry point
// ---------------------------------------------------------------------------
typedef CUresult (*EncodeTiledFn)(
    CUtensorMap*, CUtensorMapDataType, cuuint32_t, void*,
    const cuuint64_t*, const cuuint64_t*, const cuuint32_t*, const cuuint32_t*,
    CUtensorMapInterleave, CUtensorMapSwizzle, CUtensorMapL2promotion,
    CUtensorMapFloatOOBfill);

extern "C" void kernel_launch(void* const* d_in, const int* in_sizes, int n_in,
                              void* d_out, int out_size) {
    const float* emb_i = (const float*)d_in[0];
    const float* emb_j = (const float*)d_in[1];
    float* out = (float*)d_out;

    void* repb_ptr = nullptr;
    cudaGetSymbolAddress(&repb_ptr, g_repb);

    EncodeTiledFn encode = nullptr;
    cudaDriverEntryPointQueryResult qres;
    cudaGetDriverEntryPoint("cuTensorMapEncodeTiled", (void**)&encode,
                            cudaEnableDefault, &qres);

    CUtensorMap tmap;
    cuuint64_t gdim[2]    = {(cuuint64_t)D, (cuuint64_t)NROWS};
    cuuint64_t gstride[1] = {(cuuint64_t)D * 2};            // row pitch bytes
    cuuint32_t box[2]     = {KC, TILE};                     // 64 x 128 elems
    cuuint32_t estride[2] = {1, 1};
    encode(&tmap, CU_TENSOR_MAP_DATA_TYPE_BFLOAT16, 2, repb_ptr,
           gdim, gstride, box, estride,
           CU_TENSOR_MAP_INTERLEAVE_NONE, CU_TENSOR_MAP_SWIZZLE_128B,
           CU_TENSOR_MAP_L2_PROMOTION_L2_128B,
           CU_TENSOR_MAP_FLOAT_OOB_FILL_NONE);

    cudaFuncSetAttribute(gemm_exp_kernel,
                         cudaFuncAttributeMaxDynamicSharedMemorySize, SMEM_DYN);

    normalize_kernel<<<NROWS, 128>>>(emb_i, emb_j);
    gemm_exp_kernel<<<GRID, NT, SMEM_DYN>>>(out, tmap);
}

// round 17
// speedup vs baseline: 1.8862x; 1.0459x over previous
#include <cuda_runtime.h>
#include <cuda.h>
#include <cuda_bf16.h>
#include <math.h>
#include <cstdint>

// ---------------------------------------------------------------------------
// Problem constants
// ---------------------------------------------------------------------------
#define NROWS 8192       // 4B rows in rep
#define HALF  4096       // rows per input
#define D     512        // embedding dim

// GEMM config: 128x128 CTA tile, 8 warps of 64x32, K chunked by 64 bf16
#define TILE    128
#define KC      64
#define NCHUNK  (D / KC)           // 8
#define NT      256
#define NSTAGE  3
#define OP_B    (TILE * KC * 2)    // 16384 B per operand per stage
#define SLOT_B  (2 * OP_B)         // A + B per stage = 32 KB
#define SMEM_DYN (2048 + NSTAGE * SLOT_B)  // hdr/align + 3 stages = 100352 B

#define NTILES  2080               // 64*65/2 upper-triangular 128x128 tiles
#define GRID    296                // persistent CTAs, 2 per SM

// ---------------------------------------------------------------------------
// Static scratch
// ---------------------------------------------------------------------------
__device__ __align__(16) __nv_bfloat16 g_repb[(size_t)NROWS * D];  // 8 MB
__device__ double g_acc[2];        // [0] = S_offdiag (x2), [1] = nominator
__device__ unsigned int g_done;    // CTA arrival counter (self-resetting)
__device__ unsigned int g_next;    // dynamic tile counter (self-resetting)

// ---------------------------------------------------------------------------
// Helpers
// ---------------------------------------------------------------------------
__device__ __forceinline__ uint32_t smem_u32(const void* p) {
    uint32_t a;
    asm("{ .reg .u64 t; cvta.to.shared.u64 t, %1; cvt.u32.u64 %0, t; }"
        : "=r"(a) : "l"(p));
    return a;
}

#define MBAR_INIT(addr, cnt) \
    asm volatile("mbarrier.init.shared.b64 [%0], %1;" :: "r"(addr), "r"(cnt) : "memory")

#define MBAR_ARRIVE(addr) \
    asm volatile("mbarrier.arrive.shared.b64 _, [%0];" :: "r"(addr) : "memory")

#define MBAR_WAIT(addr, par) do {                                              \
    uint32_t _m = (addr), _p = (par), _d;                                      \
    asm volatile("{\n\t.reg .pred p;\n\t"                                      \
        "mbarrier.try_wait.parity.acquire.cta.shared::cta.b64 p, [%1], %2;\n\t"\
        "selp.b32 %0, 1, 0, p;\n\t}"                                           \
        : "=r"(_d) : "r"(_m), "r"(_p) : "memory");                             \
    if (!_d) {                                                                 \
        asm volatile("{\n\t.reg .pred P1;\n\t"                                 \
            "W%=:\n\t"                                                         \
            "mbarrier.try_wait.parity.acquire.cta.shared::cta.b64 P1, [%0], %1, 0x989680;\n\t" \
            "@P1 bra.uni DN%=;\n\tbra.uni W%=;\n\tDN%=:\n\t}"                  \
            :: "r"(_m), "r"(_p) : "memory");                                   \
    }                                                                          \
} while (0)

// TMA: arm barrier for 32KB and issue A+B box loads (64 x 128 bf16, SW128)
__device__ __forceinline__ void tma_issue(uint32_t bar, uint32_t dstA, uint32_t dstB,
                                          const CUtensorMap* tm,
                                          int kx, int rowA, int rowB) {
    asm volatile("mbarrier.arrive.expect_tx.shared.b64 _, [%0], %1;"
                 :: "r"(bar), "r"(32768u) : "memory");
    asm volatile("cp.async.bulk.tensor.2d.shared::cta.global.tile.mbarrier::complete_tx::bytes "
                 "[%0], [%1, {%2, %3}], [%4];"
                 :: "r"(dstA), "l"(tm), "r"(kx), "r"(rowA), "r"(bar) : "memory");
    asm volatile("cp.async.bulk.tensor.2d.shared::cta.global.tile.mbarrier::complete_tx::bytes "
                 "[%0], [%1, {%2, %3}], [%4];"
                 :: "r"(dstB), "l"(tm), "r"(kx), "r"(rowB), "r"(bar) : "memory");
}

__device__ __forceinline__ void ldmx4(uint32_t& r0, uint32_t& r1,
                                      uint32_t& r2, uint32_t& r3, uint32_t a) {
    asm volatile("ldmatrix.sync.aligned.m8n8.x4.shared.b16 {%0,%1,%2,%3}, [%4];"
                 : "=r"(r0), "=r"(r1), "=r"(r2), "=r"(r3) : "r"(a));
}

__device__ __forceinline__ void mma16816(float* c, const uint32_t* a,
                                         const uint32_t* b) {
    asm volatile(
        "mma.sync.aligned.m16n8k16.row.col.f32.bf16.bf16.f32 "
        "{%0,%1,%2,%3}, {%4,%5,%6,%7}, {%8,%9}, {%0,%1,%2,%3};"
        : "+f"(c[0]), "+f"(c[1]), "+f"(c[2]), "+f"(c[3])
        : "r"(a[0]), "r"(a[1]), "r"(a[2]), "r"(a[3]), "r"(b[0]), "r"(b[1]));
}

// exp(2x) = 2^(x * 2*log2(e)) via MUFU.EX2 — 2 instructions, idle pipe.
__device__ __forceinline__ float exp2dot_mufu(float x) {
    float y;
    asm("ex2.approx.f32 %0, %1;" : "=f"(y) : "f"(x * 2.88539008177792681f));
    return y;
}

// Decode linear upper-triangular tile index -> (bi, bj), bj >= bi, 64 rows.
__device__ __forceinline__ void decode_tile(int t, int& bi, int& bj) {
    int b = (int)((129.0f - sqrtf(16641.0f - 8.0f * (float)t)) * 0.5f);
    if (b > 63) b = 63;
    while (b * (129 - b) / 2 > t) b--;
    while ((b + 1) * (129 - (b + 1)) / 2 <= t) b++;
    bi = b;
    bj = b + (t - b * (129 - b) / 2);
}

// ---------------------------------------------------------------------------
// K1: L2-normalize rows of [emb_i; emb_j] -> bf16 g_repb. One block per row.
// Block 0 also zeroes the accumulators.
// ---------------------------------------------------------------------------
__global__ void normalize_kernel(const float* __restrict__ a,
                                 const float* __restrict__ b) {
    int row = blockIdx.x;
    int tid = threadIdx.x;  // 128
    if (row == 0 && tid == 0) { g_acc[0] = 0.0; g_acc[1] = 0.0; }

    const float* src = (row < HALF) ? (a + (size_t)row * D)
                                    : (b + (size_t)(row - HALF) * D);

    float4 v = reinterpret_cast<const float4*>(src)[tid];
    float ss = v.x * v.x + v.y * v.y + v.z * v.z + v.w * v.w;

    #pragma unroll
    for (int o = 16; o > 0; o >>= 1)
        ss += __shfl_xor_sync(0xFFFFFFFFu, ss, o);

    __shared__ float ws[4];
    int wid = tid >> 5, lane = tid & 31;
    if (lane == 0) ws[wid] = ss;
    __syncthreads();

    float total = ws[0] + ws[1] + ws[2] + ws[3];
    float inv = rsqrtf(fmaxf(total, 1e-24f));  // == x / max(norm, 1e-12)

    __nv_bfloat162 lo = __floats2bfloat162_rn(v.x * inv, v.y * inv);
    __nv_bfloat162 hi = __floats2bfloat162_rn(v.z * inv, v.w * inv);
    uint2 pk;
    pk.x = *reinterpret_cast<uint32_t*>(&lo);
    pk.y = *reinterpret_cast<uint32_t*>(&hi);
    reinterpret_cast<uint2*>(g_repb + (size_t)row * D)[tid] = pk;
}

// ---------------------------------------------------------------------------
// K2: PERSISTENT bf16 mma.sync GEMM, dynamic work-stealing, continuous TMA
// ring. Tile-boundary fetch happens BEFORE the epilogue so warps slide from
// register-only epilogue math straight into the next tile's mainloop
// (no re-phase-locking barrier). Epilogue specialized per tile class.
// ---------------------------------------------------------------------------
__global__ __launch_bounds__(NT, 2)
void gemm_exp_kernel(float* __restrict__ out,
                     const __grid_constant__ CUtensorMap tmap) {
    extern __shared__ char smraw[];
    uint32_t raw  = smem_u32(smraw);
    uint32_t base = (raw + 1023u) & ~1023u;   // 1024-align (SW128 atom span)
    uint32_t stg  = base + 1024;
    // header: full[s]@base+8s, empty[s]@base+32+8s, wred@base+128, bc@base+192

    const int tid    = threadIdx.x;
    const int wid    = tid >> 5;
    const int lane   = tid & 31;
    const int warp_m = wid & 1;
    const int warp_n = wid >> 1;

    if (tid == 0) {
        #pragma unroll
        for (int s = 0; s < NSTAGE; s++) {
            MBAR_INIT(base + 8 * s, 1);        // full[s]
            MBAR_INIT(base + 32 + 8 * s, 8);   // empty[s]
        }
    }
    __syncthreads();

    // Fetch first two tiles (work-stealing)
    const uint32_t bc = base + 192;
    if (tid == 0) {
        uint32_t t0 = atomicAdd(&g_next, 2u);
        asm volatile("st.shared.v2.u32 [%0], {%1, %2};"
                     :: "r"(bc), "r"(t0), "r"(t0 + 1u) : "memory");
    }
    __syncthreads();
    int tC, tN;
    asm volatile("ld.shared.v2.u32 {%0, %1}, [%2];"
                 : "=r"(tC), "=r"(tN) : "r"(bc));

    int biC = 0, bjC = 0, biN = 0, bjN = 0;
    bool haveC = tC < NTILES;
    bool haveN = tN < NTILES;
    if (haveC) decode_tile(tC, biC, bjC);
    if (haveN) decode_tile(tN, biN, bjN);

    // Per-lane ldmatrix address components (SW128 swizzle-aware)
    const int a_row = lane & 15;
    const int a_hi  = lane >> 4;
    const int a_sw  = a_row & 7;
    const int b_n   = ((lane >> 4) << 3) + (lane & 7);
    const int b_hi  = (lane >> 3) & 1;
    const int b_sw  = b_n & 7;
    const int grp   = lane >> 2;
    const int tig   = lane & 3;

    float sumT = 0.0f, nomT = 0.0f;
    int L = 0, slot = 0, par = 0;

    if (haveC) {
        // Prologue: arm chunks 0..2 of the first tile
        if (tid == 0) {
            #pragma unroll
            for (int s = 0; s < NSTAGE; s++) {
                uint32_t sl = stg + (uint32_t)s * SLOT_B;
                tma_issue(base + 8 * s, sl, sl + OP_B, &tmap,
                          s * KC, biC * TILE, bjC * TILE);
            }
        }

        #pragma unroll 1
        while (true) {
            float acc[4][4][4];
            #pragma unroll
            for (int mf = 0; mf < 4; mf++)
                #pragma unroll
                for (int nf = 0; nf < 4; nf++)
                    #pragma unroll
                    for (int e = 0; e < 4; e++)
                        acc[mf][nf][e] = 0.0f;

            #pragma unroll 1
            for (int j = 0; j < NCHUNK; j++) {
                MBAR_WAIT(base + 8 * slot, par);

                uint32_t sA = stg + (uint32_t)slot * SLOT_B;
                uint32_t sB = sA + OP_B;

                #pragma unroll
                for (int ks = 0; ks < 4; ks++) {
                    uint32_t afr[4][4];
                    #pragma unroll
                    for (int mf = 0; mf < 4; mf++) {
                        int grow = warp_m * 64 + mf * 16 + a_row;
                        uint32_t ca = (uint32_t)((2 * ks + a_hi) ^ a_sw);
                        ldmx4(afr[mf][0], afr[mf][1], afr[mf][2], afr[mf][3],
                              sA + grow * 128 + ca * 16);
                    }
                    uint32_t bfr[4][2];
                    #pragma unroll
                    for (int np = 0; np < 2; np++) {
                        int gn = warp_n * 32 + np * 16 + b_n;
                        uint32_t cb = (uint32_t)((2 * ks + b_hi) ^ b_sw);
                        uint32_t r0, r1, r2, r3;
                        ldmx4(r0, r1, r2, r3, sB + gn * 128 + cb * 16);
                        bfr[2 * np][0] = r0;     bfr[2 * np][1] = r1;
                        bfr[2 * np + 1][0] = r2; bfr[2 * np + 1][1] = r3;
                    }
                    #pragma unroll
                    for (int mf = 0; mf < 4; mf++)
                        #pragma unroll
                        for (int nf = 0; nf < 4; nf++)
                            mma16816(acc[mf][nf], afr[mf], bfr[nf]);
                }

                // Slot recycle: re-arm chunk j+3 — of this tile for j<5,
                // of the NEXT tile for j>=5 (if one exists).
                bool rearm = (j < NCHUNK - NSTAGE) | haveN;
                if (rearm && lane == 0) {
                    MBAR_ARRIVE(base + 32 + 8 * slot);
                    if (wid == (L & 7)) {
                        MBAR_WAIT(base + 32 + 8 * slot, par);
                        int koff = ((j + NSTAGE) & (NCHUNK - 1)) * KC;
                        bool cur = (j < NCHUNK - NSTAGE);
                        int rA = (cur ? biC : biN) * TILE;
                        int rB = (cur ? bjC : bjN) * TILE;
                        tma_issue(base + 8 * slot, sA, sB, &tmap, koff, rA, rB);
                    }
                }

                L++;
                if (++slot == NSTAGE) { slot = 0; par ^= 1; }
            }

            // Save this tile's class for the (deferred) epilogue, then do
            // the tile fetch FIRST so the epilogue can overlap the next
            // tile's mainloop across warps (no barrier after epilogue).
            const bool diag = (biC == bjC);
            const int  dbj  = bjC - biC;
            const bool nomt = (dbj == 16) | (dbj == 32) | (dbj == 48);
            const bool cont = haveN;

            if (haveN) {
                biC = biN; bjC = bjN;
                __syncthreads();   // all warps read previous broadcast
                if (tid == 0) {
                    uint32_t t = atomicAdd(&g_next, 1u);
                    asm volatile("st.shared.u32 [%0], %1;"
                                 :: "r"(bc), "r"(t) : "memory");
                }
                __syncthreads();
                asm volatile("ld.shared.u32 %0, [%1];" : "=r"(tN) : "r"(bc));
                haveN = tN < NTILES;
                if (haveN) decode_tile(tN, biN, bjN);
            }

            // Epilogue (register-only; runs warp-independently, overlapping
            // other warps' next-tile MMAs). Three specialized paths.
            if (diag) {
                #pragma unroll
                for (int mf = 0; mf < 4; mf++)
                    #pragma unroll
                    for (int nf = 0; nf < 4; nf++) {
                        int m0 = warp_m * 64 + mf * 16 + grp;
                        int n0 = warp_n * 32 + nf * 8 + tig * 2;
                        #pragma unroll
                        for (int e = 0; e < 4; e++) {
                            int mm = m0 + (e >> 1) * 8;
                            int nn = n0 + (e & 1);
                            float ex = exp2dot_mufu(acc[mf][nf][e]);
                            if (nn > mm) sumT += ex;
                        }
                    }
            } else if (nomt) {
                #pragma unroll
                for (int mf = 0; mf < 4; mf++)
                    #pragma unroll
                    for (int nf = 0; nf < 4; nf++) {
                        int m0 = warp_m * 64 + mf * 16 + grp;
                        int n0 = warp_n * 32 + nf * 8 + tig * 2;
                        #pragma unroll
                        for (int e = 0; e < 4; e++) {
                            int mm = m0 + (e >> 1) * 8;
                            int nn = n0 + (e & 1);
                            float ex = exp2dot_mufu(acc[mf][nf][e]);
                            sumT += ex;
                            if (nn == mm) nomT += ex;
                        }
                    }
            } else {
                // Plain off-diagonal tile: every element counts, no masks.
                #pragma unroll
                for (int mf = 0; mf < 4; mf++)
                    #pragma unroll
                    for (int nf = 0; nf < 4; nf++)
                        #pragma unroll
                        for (int e = 0; e < 4; e++)
                            sumT += exp2dot_mufu(acc[mf][nf][e]);
            }

            if (!cont) break;
        }
    }

    // Final reduction: shfl in-warp, 8 partials in header smem, warp 0 ends.
    #pragma unroll
    for (int o = 16; o > 0; o >>= 1) {
        sumT += __shfl_xor_sync(0xFFFFFFFFu, sumT, o);
        nomT += __shfl_xor_sync(0xFFFFFFFFu, nomT, o);
    }
    uint32_t wred = base + 128;
    if (lane == 0)
        asm volatile("st.shared.v2.f32 [%0], {%1, %2};"
                     :: "r"(wred + 8u * wid), "f"(sumT), "f"(nomT) : "memory");
    __syncthreads();
    if (wid == 0) {
        float2 v2 = make_float2(0.0f, 0.0f);
        if (lane < 8)
            asm volatile("ld.shared.v2.f32 {%0, %1}, [%2];"
                         : "=f"(v2.x), "=f"(v2.y) : "r"(wred + 8u * lane));
        #pragma unroll
        for (int o = 4; o > 0; o >>= 1) {
            v2.x += __shfl_xor_sync(0xFFFFFFFFu, v2.x, o);
            v2.y += __shfl_xor_sync(0xFFFFFFFFu, v2.y, o);
        }
        if (lane == 0) {
            atomicAdd(&g_acc[0], 2.0 * (double)v2.x);   // mirror lower triangle
            if (v2.y != 0.0f) atomicAdd(&g_acc[1], 2.0 * (double)v2.y);

            // Last-CTA finalize (+ reset counters for graph replay)
            __threadfence();
            unsigned int t = atomicAdd(&g_done, 1u);
            if (t == GRID - 1) {
                __threadfence();
                double nomv = g_acc[1];
                double den  = g_acc[0] - nomv;
                out[0] = (float)(-log(nomv / den) / (double)NROWS);
                g_done = 0;
                g_next = 0;
            }
        }
    }
}

// ---------------------------------------------------------------------------
// Entry point
// ---------------------------------------------------------------------------
typedef CUresult (*EncodeTiledFn)(
    CUtensorMap*, CUtensorMapDataType, cuuint32_t, void*,
    const cuuint64_t*, const cuuint64_t*, const cuuint32_t*, const cuuint32_t*,
    CUtensorMapInterleave, CUtensorMapSwizzle, CUtensorMapL2promotion,
    CUtensorMapFloatOOBfill);

extern "C" void kernel_launch(void* const* d_in, const int* in_sizes, int n_in,
                              void* d_out, int out_size) {
    const float* emb_i = (const float*)d_in[0];
    const float* emb_j = (const float*)d_in[1];
    float* out = (float*)d_out;

    void* repb_ptr = nullptr;
    cudaGetSymbolAddress(&repb_ptr, g_repb);

    EncodeTiledFn encode = nullptr;
    cudaDriverEntryPointQueryResult qres;
    cudaGetDriverEntryPoint("cuTensorMapEncodeTiled", (void**)&encode,
                            cudaEnableDefault, &qres);

    CUtensorMap tmap;
    cuuint64_t gdim[2]    = {(cuuint64_t)D, (cuuint64_t)NROWS};
    cuuint64_t gstride[1] = {(cuuint64_t)D * 2};            // row pitch bytes
    cuuint32_t box[2]     = {KC, TILE};                     // 64 x 128 elems
    cuuint32_t estride[2] = {1, 1};
    encode(&tmap, CU_TENSOR_MAP_DATA_TYPE_BFLOAT16, 2, repb_ptr,
           gdim, gstride, box, estride,
           CU_TENSOR_MAP_INTERLEAVE_NONE, CU_TENSOR_MAP_SWIZZLE_128B,
           CU_TENSOR_MAP_L2_PROMOTION_L2_128B,
           CU_TENSOR_MAP_FLOAT_OOB_FILL_NONE);

    cudaFuncSetAttribute(gemm_exp_kernel,
                         cudaFuncAttributeMaxDynamicSharedMemorySize, SMEM_DYN);

    normalize_kernel<<<NROWS, 128>>>(emb_i, emb_j);
    gemm_exp_kernel<<<GRID, NT, SMEM_DYN>>>(out, tmap);
}